// round 1
// baseline (speedup 1.0000x reference)
#include <cuda_runtime.h>

#define NN 100000
#define NE 1600000

// ---------------- scratch (device globals; no allocation allowed) ----------
__device__ __align__(128) int   g_deg[2 * NN];        // [0,NN): out-deg, [NN,2NN): in-deg
__device__ __align__(128) float g_onorm[NN];
__device__ __align__(128) float g_inorm[NN];
__device__ __align__(128) float g_h1[(size_t)NN * 64];    // (x*onorm)@W1
__device__ __align__(128) float g_agg1[(size_t)NN * 64];  // segment-sum of h1[src] into dst
__device__ __align__(128) float g_h2[(size_t)NN * 40];    // (x1*onorm)@W2

// sm_90+ vector float reduction (no return) — 4x fewer L2 atomic ops
__device__ __forceinline__ void red_add_v4(float* addr, float4 v) {
    asm volatile("red.global.add.v4.f32 [%0], {%1,%2,%3,%4};"
                 :: "l"(addr), "f"(v.x), "f"(v.y), "f"(v.z), "f"(v.w)
                 : "memory");
}

// ---------------- degrees ----------------
__global__ void k_degree(const int* __restrict__ src, const int* __restrict__ dst) {
    int i = blockIdx.x * 256 + threadIdx.x;
    if (i < NE) {
        atomicAdd(&g_deg[__ldg(&src[i])], 1);
        atomicAdd(&g_deg[NN + __ldg(&dst[i])], 1);
    }
}

__global__ void k_norm() {
    int i = blockIdx.x * 256 + threadIdx.x;
    if (i < NN) {
        g_onorm[i] = rsqrtf(fmaxf((float)g_deg[i], 1.0f));
        g_inorm[i] = rsqrtf(fmaxf((float)g_deg[NN + i], 1.0f));
    }
}

// ---------------- GEMM1: h1 = (x * onorm) @ W1   [100k x 256] @ [256 x 64] ----
// 256 threads/block, 64 nodes/block. Thread = (node, 16-column slice).
// W1 (64KB) in dynamic smem; 64 FFMA per (1 LDG.128 + 16 LDS.128) -> FFMA bound.
__global__ void k_gemm1(const float* __restrict__ x, const float* __restrict__ W1) {
    extern __shared__ float sW[];   // 256*64 floats = 64KB
    for (int i = threadIdx.x; i < 256 * 64; i += 256) sW[i] = W1[i];
    __syncthreads();

    int node = blockIdx.x * 64 + (threadIdx.x >> 2);
    if (node >= NN) return;
    int jg = (threadIdx.x & 3) * 16;

    float acc[16];
#pragma unroll
    for (int j = 0; j < 16; j++) acc[j] = 0.f;

    const float4* xr = reinterpret_cast<const float4*>(x + (size_t)node * 256);
#pragma unroll 8
    for (int k4 = 0; k4 < 64; k4++) {
        float4 xv = __ldg(&xr[k4]);
        float xs[4] = {xv.x, xv.y, xv.z, xv.w};
#pragma unroll
        for (int c = 0; c < 4; c++) {
            const float4* wr = reinterpret_cast<const float4*>(&sW[(k4 * 4 + c) * 64 + jg]);
#pragma unroll
            for (int q = 0; q < 4; q++) {
                float4 w = wr[q];
                acc[q * 4 + 0] += xs[c] * w.x;
                acc[q * 4 + 1] += xs[c] * w.y;
                acc[q * 4 + 2] += xs[c] * w.z;
                acc[q * 4 + 3] += xs[c] * w.w;
            }
        }
    }

    float nrm = g_onorm[node];
    float4* o = reinterpret_cast<float4*>(&g_h1[(size_t)node * 64 + jg]);
#pragma unroll
    for (int q = 0; q < 4; q++)
        o[q] = make_float4(acc[q * 4 + 0] * nrm, acc[q * 4 + 1] * nrm,
                           acc[q * 4 + 2] * nrm, acc[q * 4 + 3] * nrm);
}

// ---------------- scatter layer 1: agg1[dst] += h1[src]  (64 floats/edge) ----
// thread = (edge, float4-slot). h1/agg1 are L2-resident (25.6MB each).
__global__ void k_scatter1(const int* __restrict__ src, const int* __restrict__ dst) {
    int idx = blockIdx.x * 256 + threadIdx.x;
    if (idx >= NE * 16) return;
    int e = idx >> 4, c = idx & 15;
    int s = __ldg(&src[e]), d = __ldg(&dst[e]);
    float4 v = *reinterpret_cast<const float4*>(&g_h1[(size_t)s * 64 + c * 4]);
    red_add_v4(&g_agg1[(size_t)d * 64 + c * 4], v);
}

// ---------------- GEMM2 (fused): h2 = ((agg1*inorm + b1) * onorm) @ W2 -------
// [100k x 64] @ [64 x 40]. W2 (10KB) + b1 in smem. Thread = node, 40 accs.
__global__ void k_gemm2(const float* __restrict__ W2, const float* __restrict__ b1) {
    __shared__ float sW[64 * 40];
    __shared__ float sb[64];
    for (int i = threadIdx.x; i < 64 * 40; i += 256) sW[i] = W2[i];
    if (threadIdx.x < 64) sb[threadIdx.x] = b1[threadIdx.x];
    __syncthreads();

    int n = blockIdx.x * 256 + threadIdx.x;
    if (n >= NN) return;
    float ni = g_inorm[n], no = g_onorm[n];

    float acc[40];
#pragma unroll
    for (int j = 0; j < 40; j++) acc[j] = 0.f;

    const float4* ar = reinterpret_cast<const float4*>(&g_agg1[(size_t)n * 64]);
#pragma unroll 4
    for (int k4 = 0; k4 < 16; k4++) {
        float4 a = ar[k4];
        float av[4] = {a.x, a.y, a.z, a.w};
#pragma unroll
        for (int c = 0; c < 4; c++) {
            int k = k4 * 4 + c;
            float xv = av[c] * ni + sb[k];       // fused layer-1 epilogue
            const float4* wr = reinterpret_cast<const float4*>(&sW[k * 40]);
#pragma unroll
            for (int q = 0; q < 10; q++) {
                float4 w = wr[q];
                acc[q * 4 + 0] += xv * w.x;
                acc[q * 4 + 1] += xv * w.y;
                acc[q * 4 + 2] += xv * w.z;
                acc[q * 4 + 3] += xv * w.w;
            }
        }
    }

    float4* o = reinterpret_cast<float4*>(&g_h2[(size_t)n * 40]);
#pragma unroll
    for (int q = 0; q < 10; q++)
        o[q] = make_float4(acc[q * 4 + 0] * no, acc[q * 4 + 1] * no,
                           acc[q * 4 + 2] * no, acc[q * 4 + 3] * no);
}

// ---------------- scatter layer 2: out[dst] += h2[src]  (40 floats/edge) ----
__global__ void k_scatter2(const int* __restrict__ src, const int* __restrict__ dst,
                           float* __restrict__ out) {
    int idx = blockIdx.x * 256 + threadIdx.x;
    if (idx >= NE * 10) return;
    int e = idx / 10, c = idx - e * 10;
    int s = __ldg(&src[e]), d = __ldg(&dst[e]);
    float4 v = *reinterpret_cast<const float4*>(&g_h2[(size_t)s * 40 + c * 4]);
    red_add_v4(out + (size_t)d * 40 + c * 4, v);
}

// ---------------- epilogue: out = out * inorm + b2 --------------------------
__global__ void k_final(float* __restrict__ out, const float* __restrict__ b2) {
    int idx = blockIdx.x * 256 + threadIdx.x;
    if (idx >= NN * 10) return;
    int n = idx / 10, c = idx - n * 10;
    float4 v = reinterpret_cast<float4*>(out)[idx];
    float ni = g_inorm[n];
    float4 bb = reinterpret_cast<const float4*>(b2)[c];
    reinterpret_cast<float4*>(out)[idx] =
        make_float4(v.x * ni + bb.x, v.y * ni + bb.y, v.z * ni + bb.z, v.w * ni + bb.w);
}

extern "C" void kernel_launch(void* const* d_in, const int* in_sizes, int n_in,
                              void* d_out, int out_size) {
    const float* x  = (const float*)d_in[0];
    const int*   src = (const int*)d_in[1];
    const int*   dst = (const int*)d_in[2];
    const float* W1 = (const float*)d_in[3];
    const float* b1 = (const float*)d_in[4];
    const float* W2 = (const float*)d_in[5];
    const float* b2 = (const float*)d_in[6];
    float* out = (float*)d_out;

    void *p_deg, *p_agg1;
    cudaGetSymbolAddress(&p_deg, g_deg);
    cudaGetSymbolAddress(&p_agg1, g_agg1);

    // zero accumulators (captured as memset nodes)
    cudaMemsetAsync(p_deg, 0, sizeof(int) * 2 * NN, 0);
    cudaMemsetAsync(p_agg1, 0, sizeof(float) * (size_t)NN * 64, 0);
    cudaMemsetAsync(d_out, 0, sizeof(float) * (size_t)NN * 40, 0);

    cudaFuncSetAttribute(k_gemm1, cudaFuncAttributeMaxDynamicSharedMemorySize, 256 * 64 * 4);

    k_degree<<<(NE + 255) / 256, 256>>>(src, dst);
    k_norm<<<(NN + 255) / 256, 256>>>();
    k_gemm1<<<(NN + 63) / 64, 256, 256 * 64 * 4>>>(x, W1);
    k_scatter1<<<(NE * 16 + 255) / 256, 256>>>(src, dst);
    k_gemm2<<<(NN + 255) / 256, 256>>>(W2, b1);
    k_scatter2<<<(NE * 10 + 255) / 256, 256>>>(src, dst, out);
    k_final<<<(NN * 10 + 255) / 256, 256>>>(out, b2);
}

// round 4
// speedup vs baseline: 1.6355x; 1.6355x over previous
#include <cuda_runtime.h>

#define NN 100000
#define NE 1600000
#define NB ((NN + 255) / 256)   // 391 blocks for node-sized kernels

// ---------------- scratch (device globals; no allocation allowed) ----------
__device__ __align__(128) int   g_deg[2 * NN];        // [0,NN): out-deg, [NN,2NN): in-deg
__device__ __align__(128) float g_onorm[NN];
__device__ __align__(128) float g_inorm[NN];
__device__ __align__(128) float g_h1[(size_t)NN * 64];    // (x*onorm)@W1
__device__ __align__(128) float g_agg1[(size_t)NN * 64];  // sum over in-edges of h1[src]
__device__ __align__(128) float g_h2[(size_t)NN * 40];    // layer-2 transformed feats
__device__ __align__(128) int   g_csr[NE];                // src ids grouped by dst
__device__ __align__(128) int   g_rowstart[NN];
__device__ __align__(128) int   g_cursor[NN];
__device__ __align__(128) int   g_bsum[NB + 1];
__device__ __align__(128) int   g_bpre[NB + 1];

// ---------------- degrees ----------------
__global__ void k_degree(const int* __restrict__ src, const int* __restrict__ dst) {
    int i = blockIdx.x * 256 + threadIdx.x;
    if (i < NE) {
        atomicAdd(&g_deg[__ldg(&src[i])], 1);
        atomicAdd(&g_deg[NN + __ldg(&dst[i])], 1);
    }
}

__global__ void k_norm() {
    int i = blockIdx.x * 256 + threadIdx.x;
    if (i < NN) {
        g_onorm[i] = rsqrtf(fmaxf((float)g_deg[i], 1.0f));
        g_inorm[i] = rsqrtf(fmaxf((float)g_deg[NN + i], 1.0f));
    }
}

// ---------------- CSR build: 3-step block scan of in-degree -----------------
__global__ void k_scan_block() {
    __shared__ int s[256];
    int n = blockIdx.x * 256 + threadIdx.x;
    int v = (n < NN) ? g_deg[NN + n] : 0;
    s[threadIdx.x] = v;
    __syncthreads();
    for (int off = 128; off > 0; off >>= 1) {
        if (threadIdx.x < off) s[threadIdx.x] += s[threadIdx.x + off];
        __syncthreads();
    }
    if (threadIdx.x == 0) g_bsum[blockIdx.x] = s[0];
}

__global__ void k_scan_top() {
    if (threadIdx.x == 0) {
        int run = 0;
        for (int b = 0; b < NB; b++) { g_bpre[b] = run; run += g_bsum[b]; }
    }
}

__global__ void k_scan_apply() {
    __shared__ int s[256];
    int n = blockIdx.x * 256 + threadIdx.x;
    int v = (n < NN) ? g_deg[NN + n] : 0;
    s[threadIdx.x] = v;
    __syncthreads();
    // Hillis-Steele inclusive scan
    for (int off = 1; off < 256; off <<= 1) {
        int t = (threadIdx.x >= off) ? s[threadIdx.x - off] : 0;
        __syncthreads();
        s[threadIdx.x] += t;
        __syncthreads();
    }
    int excl = s[threadIdx.x] - v;
    int rs = g_bpre[blockIdx.x] + excl;
    if (n < NN) { g_rowstart[n] = rs; g_cursor[n] = rs; }
}

__global__ void k_build(const int* __restrict__ src, const int* __restrict__ dst) {
    int e = blockIdx.x * 256 + threadIdx.x;
    if (e < NE) {
        int d = __ldg(&dst[e]);
        int p = atomicAdd(&g_cursor[d], 1);
        g_csr[p] = __ldg(&src[e]);
    }
}

// ---------------- GEMM1: h1 = (x * onorm) @ W1   [100k x 256]@[256 x 64] ----
// 256 threads/block covering 128 nodes; thread = (node-pair, 16-col slice).
// Each W fragment from smem feeds TWO nodes -> LDS:FFMA = 1:8, FFMA-bound.
__global__ void k_gemm1(const float* __restrict__ x, const float* __restrict__ W1) {
    extern __shared__ float sW[];   // 256*64 floats = 64KB
    for (int i = threadIdx.x; i < 256 * 64; i += 256) sW[i] = W1[i];
    __syncthreads();

    int pair = threadIdx.x >> 2;
    int jg = (threadIdx.x & 3) * 16;
    int n0 = blockIdx.x * 128 + pair;
    int n1 = n0 + 64;
    bool v0 = n0 < NN, v1 = n1 < NN;
    if (!v0) return;

    float acc0[16], acc1[16];
#pragma unroll
    for (int j = 0; j < 16; j++) { acc0[j] = 0.f; acc1[j] = 0.f; }

    const float4* xr0 = reinterpret_cast<const float4*>(x + (size_t)n0 * 256);
    const float4* xr1 = reinterpret_cast<const float4*>(x + (size_t)(v1 ? n1 : n0) * 256);

#pragma unroll 4
    for (int k4 = 0; k4 < 64; k4++) {
        float4 xa = __ldg(&xr0[k4]);
        float4 xb = __ldg(&xr1[k4]);
        float xs0[4] = {xa.x, xa.y, xa.z, xa.w};
        float xs1[4] = {xb.x, xb.y, xb.z, xb.w};
#pragma unroll
        for (int c = 0; c < 4; c++) {
            const float4* wr = reinterpret_cast<const float4*>(&sW[(k4 * 4 + c) * 64 + jg]);
#pragma unroll
            for (int q = 0; q < 4; q++) {
                float4 w = wr[q];
                acc0[q * 4 + 0] += xs0[c] * w.x;  acc1[q * 4 + 0] += xs1[c] * w.x;
                acc0[q * 4 + 1] += xs0[c] * w.y;  acc1[q * 4 + 1] += xs1[c] * w.y;
                acc0[q * 4 + 2] += xs0[c] * w.z;  acc1[q * 4 + 2] += xs1[c] * w.z;
                acc0[q * 4 + 3] += xs0[c] * w.w;  acc1[q * 4 + 3] += xs1[c] * w.w;
            }
        }
    }

    float nrm0 = g_onorm[n0];
    float4* o0 = reinterpret_cast<float4*>(&g_h1[(size_t)n0 * 64 + jg]);
#pragma unroll
    for (int q = 0; q < 4; q++)
        o0[q] = make_float4(acc0[q*4+0]*nrm0, acc0[q*4+1]*nrm0, acc0[q*4+2]*nrm0, acc0[q*4+3]*nrm0);
    if (v1) {
        float nrm1 = g_onorm[n1];
        float4* o1 = reinterpret_cast<float4*>(&g_h1[(size_t)n1 * 64 + jg]);
#pragma unroll
        for (int q = 0; q < 4; q++)
            o1[q] = make_float4(acc1[q*4+0]*nrm1, acc1[q*4+1]*nrm1, acc1[q*4+2]*nrm1, acc1[q*4+3]*nrm1);
    }
}

// ---------------- agg1: warp per node, gather-only (no atomics) -------------
// lanes split into 2 groups of 16; each group handles edges strided by 2;
// 2x unrolled (4 independent float4 loads in flight per warp).
__global__ void k_agg1() {
    int w = (blockIdx.x * 256 + threadIdx.x) >> 5;
    if (w >= NN) return;
    int lane = threadIdx.x & 31;
    int grp = lane >> 4, c = lane & 15;

    int beg = g_rowstart[w];
    int end = beg + g_deg[NN + w];

    float4 a0 = make_float4(0.f, 0.f, 0.f, 0.f);
    float4 a1 = make_float4(0.f, 0.f, 0.f, 0.f);
    int j = beg + grp;
    for (; j + 2 < end; j += 4) {
        int s0 = __ldg(&g_csr[j]);
        int s1 = __ldg(&g_csr[j + 2]);
        float4 v0 = *reinterpret_cast<const float4*>(&g_h1[(size_t)s0 * 64 + c * 4]);
        float4 v1 = *reinterpret_cast<const float4*>(&g_h1[(size_t)s1 * 64 + c * 4]);
        a0.x += v0.x; a0.y += v0.y; a0.z += v0.z; a0.w += v0.w;
        a1.x += v1.x; a1.y += v1.y; a1.z += v1.z; a1.w += v1.w;
    }
    if (j < end) {
        int s0 = __ldg(&g_csr[j]);
        float4 v0 = *reinterpret_cast<const float4*>(&g_h1[(size_t)s0 * 64 + c * 4]);
        a0.x += v0.x; a0.y += v0.y; a0.z += v0.z; a0.w += v0.w;
    }
    float4 acc = make_float4(a0.x + a1.x, a0.y + a1.y, a0.z + a1.z, a0.w + a1.w);

    acc.x += __shfl_down_sync(0xffffffffu, acc.x, 16);
    acc.y += __shfl_down_sync(0xffffffffu, acc.y, 16);
    acc.z += __shfl_down_sync(0xffffffffu, acc.z, 16);
    acc.w += __shfl_down_sync(0xffffffffu, acc.w, 16);
    if (lane < 16)
        *reinterpret_cast<float4*>(&g_agg1[(size_t)w * 64 + c * 4]) = acc;
}

// ---------------- GEMM2 (fused): h2 = ((agg1*inorm + b1) * onorm) @ W2 ------
__global__ void k_gemm2(const float* __restrict__ W2, const float* __restrict__ b1) {
    __shared__ float sW[64 * 40];
    __shared__ float sb[64];
    for (int i = threadIdx.x; i < 64 * 40; i += 256) sW[i] = W2[i];
    if (threadIdx.x < 64) sb[threadIdx.x] = b1[threadIdx.x];
    __syncthreads();

    int n = blockIdx.x * 256 + threadIdx.x;
    if (n >= NN) return;
    float ni = g_inorm[n], no = g_onorm[n];

    float acc[40];
#pragma unroll
    for (int j = 0; j < 40; j++) acc[j] = 0.f;

    const float4* ar = reinterpret_cast<const float4*>(&g_agg1[(size_t)n * 64]);
#pragma unroll 4
    for (int k4 = 0; k4 < 16; k4++) {
        float4 a = ar[k4];
        float av[4] = {a.x, a.y, a.z, a.w};
#pragma unroll
        for (int c = 0; c < 4; c++) {
            int k = k4 * 4 + c;
            float xv = av[c] * ni + sb[k];       // fused layer-1 epilogue
            const float4* wr = reinterpret_cast<const float4*>(&sW[k * 40]);
#pragma unroll
            for (int q = 0; q < 10; q++) {
                float4 w = wr[q];
                acc[q * 4 + 0] += xv * w.x;
                acc[q * 4 + 1] += xv * w.y;
                acc[q * 4 + 2] += xv * w.z;
                acc[q * 4 + 3] += xv * w.w;
            }
        }
    }

    float4* o = reinterpret_cast<float4*>(&g_h2[(size_t)n * 40]);
#pragma unroll
    for (int q = 0; q < 10; q++)
        o[q] = make_float4(acc[q*4+0]*no, acc[q*4+1]*no, acc[q*4+2]*no, acc[q*4+3]*no);
}

// ---------------- agg2: warp per node, 3 groups of 10 lanes, 2x unroll ------
// out = sum * inorm + b2 (fused final epilogue).
__global__ void k_agg2(float* __restrict__ out, const float* __restrict__ b2) {
    int w = (blockIdx.x * 256 + threadIdx.x) >> 5;
    if (w >= NN) return;
    int lane = threadIdx.x & 31;
    int grp = lane / 10;             // 0,1,2 active; lanes 30,31 -> grp 3 (idle)
    int c = lane - grp * 10;

    int beg = g_rowstart[w];
    int end = beg + g_deg[NN + w];

    float4 a0 = make_float4(0.f, 0.f, 0.f, 0.f);
    float4 a1 = make_float4(0.f, 0.f, 0.f, 0.f);
    if (grp < 3) {
        int j = beg + grp;
        for (; j + 3 < end; j += 6) {
            int s0 = __ldg(&g_csr[j]);
            int s1 = __ldg(&g_csr[j + 3]);
            float4 v0 = *reinterpret_cast<const float4*>(&g_h2[(size_t)s0 * 40 + c * 4]);
            float4 v1 = *reinterpret_cast<const float4*>(&g_h2[(size_t)s1 * 40 + c * 4]);
            a0.x += v0.x; a0.y += v0.y; a0.z += v0.z; a0.w += v0.w;
            a1.x += v1.x; a1.y += v1.y; a1.z += v1.z; a1.w += v1.w;
        }
        if (j < end) {
            int s0 = __ldg(&g_csr[j]);
            float4 v0 = *reinterpret_cast<const float4*>(&g_h2[(size_t)s0 * 40 + c * 4]);
            a0.x += v0.x; a0.y += v0.y; a0.z += v0.z; a0.w += v0.w;
        }
    }
    float4 acc = make_float4(a0.x + a1.x, a0.y + a1.y, a0.z + a1.z, a0.w + a1.w);

    float ax10 = __shfl_down_sync(0xffffffffu, acc.x, 10);
    float ay10 = __shfl_down_sync(0xffffffffu, acc.y, 10);
    float az10 = __shfl_down_sync(0xffffffffu, acc.z, 10);
    float aw10 = __shfl_down_sync(0xffffffffu, acc.w, 10);
    float ax20 = __shfl_down_sync(0xffffffffu, acc.x, 20);
    float ay20 = __shfl_down_sync(0xffffffffu, acc.y, 20);
    float az20 = __shfl_down_sync(0xffffffffu, acc.z, 20);
    float aw20 = __shfl_down_sync(0xffffffffu, acc.w, 20);
    if (lane < 10) {
        float ni = g_inorm[w];
        float4 bb = __ldg(reinterpret_cast<const float4*>(b2) + c);
        float4 r;
        r.x = (acc.x + ax10 + ax20) * ni + bb.x;
        r.y = (acc.y + ay10 + ay20) * ni + bb.y;
        r.z = (acc.z + az10 + az20) * ni + bb.z;
        r.w = (acc.w + aw10 + aw20) * ni + bb.w;
        *reinterpret_cast<float4*>(out + (size_t)w * 40 + c * 4) = r;
    }
}

extern "C" void kernel_launch(void* const* d_in, const int* in_sizes, int n_in,
                              void* d_out, int out_size) {
    const float* x   = (const float*)d_in[0];
    const int*   src = (const int*)d_in[1];
    const int*   dst = (const int*)d_in[2];
    const float* W1  = (const float*)d_in[3];
    const float* b1  = (const float*)d_in[4];
    const float* W2  = (const float*)d_in[5];
    const float* b2  = (const float*)d_in[6];
    float* out = (float*)d_out;

    void* p_deg;
    cudaGetSymbolAddress(&p_deg, g_deg);
    cudaMemsetAsync(p_deg, 0, sizeof(int) * 2 * NN, 0);

    cudaFuncSetAttribute(k_gemm1, cudaFuncAttributeMaxDynamicSharedMemorySize, 256 * 64 * 4);

    k_degree<<<(NE + 255) / 256, 256>>>(src, dst);
    k_norm<<<NB, 256>>>();
    k_scan_block<<<NB, 256>>>();
    k_scan_top<<<1, 32>>>();
    k_scan_apply<<<NB, 256>>>();
    k_build<<<(NE + 255) / 256, 256>>>(src, dst);
    k_gemm1<<<(NN + 127) / 128, 256, 256 * 64 * 4>>>(x, W1);
    k_agg1<<<(NN * 32 + 255) / 256, 256>>>();
    k_gemm2<<<NB, 256>>>(W2, b1);
    k_agg2<<<(NN * 32 + 255) / 256, 256>>>(out, b2);
}